// round 1
// baseline (speedup 1.0000x reference)
#include <cuda_runtime.h>
#include <math.h>

#define Bn 4096
#define Tn 64
#define Hn 64

#define STR 68   // padded stride for transposed smem tiles (multiple of 4)
#define XS  68

// ---------------- device scratch (allocation-free rule: __device__ globals) ----
__device__ float g_x2[(size_t)Tn * Bn * 64];   // trunk output, [T][B][64]
__device__ float g_xs[(size_t)2 * Bn * Tn];    // [2B][T]
__device__ float g_ps[(size_t)2 * Bn * Tn];    // [2B][T]

__device__ __forceinline__ float sigf(float x) {
    return __fdividef(1.f, 1.f + __expf(-x));
}
__device__ __forceinline__ float tanh_fast(float x) {
    float e = __expf(-2.f * fabsf(x));
    float t = __fdividef(1.f - e, 1.f + e);
    return copysignf(t, x);
}

// =====================================================================
// Kernel 1: MLP trunk.  x1 = relu(LN(obs@W1+b1)); x2 = relu(LN([x1,act]@W2+b2))
// Writes x2 to g_x2 in [T][B][64] layout (row i of obs: b = i/T, t = i%T).
// 256 threads, 64 rows per block. 4x4 register tiles, 16 col-threads per row.
// =====================================================================
__global__ void __launch_bounds__(256, 2) trunk_kernel(
    const float* __restrict__ obs, const float* __restrict__ act,
    const float* __restrict__ W1, const float* __restrict__ b1,
    const float* __restrict__ g1, const float* __restrict__ be1,
    const float* __restrict__ W2, const float* __restrict__ b2,
    const float* __restrict__ g2, const float* __restrict__ be2)
{
    extern __shared__ float sm[];
    float* sW1 = sm;                 // 128*64
    float* sW2 = sW1 + 128 * 64;     // 96*64
    float* sX  = sW2 + 96 * 64;      // 64 x STR (k-chunk of obs, transposed)
    float* sA  = sX + 64 * STR;      // 96 x STR (x1 | action, transposed)
    float* sP  = sA + 96 * STR;      // 6*64 params

    const int tid  = threadIdx.x;
    const int row0 = blockIdx.x * 64;

    for (int i = tid; i < 2048; i += 256) ((float4*)sW1)[i] = ((const float4*)W1)[i];
    for (int i = tid; i < 1536; i += 256) ((float4*)sW2)[i] = ((const float4*)W2)[i];
    if (tid < 64) {
        sP[tid]       = b1[tid];  sP[64 + tid]  = g1[tid];  sP[128 + tid] = be1[tid];
        sP[192 + tid] = b2[tid];  sP[256 + tid] = g2[tid];  sP[320 + tid] = be2[tid];
    }

    const int cg = tid & 15, rg = tid >> 4;
    const int c0 = cg * 4, r0 = rg * 4;
    const int lr = tid >> 2, kq = tid & 3;   // cooperative loader mapping

    float acc[4][4];
#pragma unroll
    for (int r = 0; r < 4; ++r) { acc[r][0] = 0.f; acc[r][1] = 0.f; acc[r][2] = 0.f; acc[r][3] = 0.f; }

    // GEMM1: K=128 in two chunks of 64 (saves smem -> 2 CTAs/SM)
    for (int kc = 0; kc < 2; ++kc) {
        __syncthreads();
        {
            const float* src = obs + (size_t)(row0 + lr) * 128 + kc * 64 + kq * 16;
#pragma unroll
            for (int j = 0; j < 4; ++j) {
                float4 v = *(const float4*)(src + j * 4);
                int k = kq * 16 + j * 4;
                sX[(k + 0) * STR + lr] = v.x;
                sX[(k + 1) * STR + lr] = v.y;
                sX[(k + 2) * STR + lr] = v.z;
                sX[(k + 3) * STR + lr] = v.w;
            }
        }
        __syncthreads();
#pragma unroll 4
        for (int k = 0; k < 64; ++k) {
            float4 xv = *(const float4*)(sX + k * STR + r0);
            float4 wv = *(const float4*)(sW1 + (kc * 64 + k) * 64 + c0);
            acc[0][0] += xv.x * wv.x; acc[0][1] += xv.x * wv.y; acc[0][2] += xv.x * wv.z; acc[0][3] += xv.x * wv.w;
            acc[1][0] += xv.y * wv.x; acc[1][1] += xv.y * wv.y; acc[1][2] += xv.y * wv.z; acc[1][3] += xv.y * wv.w;
            acc[2][0] += xv.z * wv.x; acc[2][1] += xv.z * wv.y; acc[2][2] += xv.z * wv.z; acc[2][3] += xv.z * wv.w;
            acc[3][0] += xv.w * wv.x; acc[3][1] += xv.w * wv.y; acc[3][2] += xv.w * wv.z; acc[3][3] += xv.w * wv.w;
        }
    }

    // LN1 + relu -> sA (transposed), cols 0..63
#pragma unroll
    for (int r = 0; r < 4; ++r) {
        float y[4]; float s = 0.f, q = 0.f;
#pragma unroll
        for (int c = 0; c < 4; ++c) { y[c] = acc[r][c] + sP[c0 + c]; s += y[c]; q += y[c] * y[c]; }
#pragma unroll
        for (int o = 8; o; o >>= 1) {
            s += __shfl_xor_sync(0xffffffffu, s, o);
            q += __shfl_xor_sync(0xffffffffu, q, o);
        }
        float m = s * 0.015625f;
        float var = q * 0.015625f - m * m;
        float rs = rsqrtf(var + 1e-12f);
#pragma unroll
        for (int c = 0; c < 4; ++c) {
            float z = (y[c] - m) * rs * sP[64 + c0 + c] + sP[128 + c0 + c];
            sA[(c0 + c) * STR + r0 + r] = fmaxf(z, 0.f);
        }
    }

    // append action -> sA cols 64..95 (transposed)
    {
        const float* asrc = act + (size_t)(row0 + lr) * 32 + kq * 8;
        float4 a0 = *(const float4*)asrc;
        float4 a1 = *(const float4*)(asrc + 4);
        int cb = 64 + kq * 8;
        sA[(cb + 0) * STR + lr] = a0.x; sA[(cb + 1) * STR + lr] = a0.y;
        sA[(cb + 2) * STR + lr] = a0.z; sA[(cb + 3) * STR + lr] = a0.w;
        sA[(cb + 4) * STR + lr] = a1.x; sA[(cb + 5) * STR + lr] = a1.y;
        sA[(cb + 6) * STR + lr] = a1.z; sA[(cb + 7) * STR + lr] = a1.w;
    }
    __syncthreads();

    // GEMM2: K=96
    float a2[4][4];
#pragma unroll
    for (int r = 0; r < 4; ++r) {
        a2[r][0] = sP[192 + c0 + 0]; a2[r][1] = sP[192 + c0 + 1];
        a2[r][2] = sP[192 + c0 + 2]; a2[r][3] = sP[192 + c0 + 3];
    }
#pragma unroll 4
    for (int k = 0; k < 96; ++k) {
        float4 xv = *(const float4*)(sA + k * STR + r0);
        float4 wv = *(const float4*)(sW2 + k * 64 + c0);
        a2[0][0] += xv.x * wv.x; a2[0][1] += xv.x * wv.y; a2[0][2] += xv.x * wv.z; a2[0][3] += xv.x * wv.w;
        a2[1][0] += xv.y * wv.x; a2[1][1] += xv.y * wv.y; a2[1][2] += xv.y * wv.z; a2[1][3] += xv.y * wv.w;
        a2[2][0] += xv.z * wv.x; a2[2][1] += xv.z * wv.y; a2[2][2] += xv.z * wv.z; a2[2][3] += xv.z * wv.w;
        a2[3][0] += xv.w * wv.x; a2[3][1] += xv.w * wv.y; a2[3][2] += xv.w * wv.z; a2[3][3] += xv.w * wv.w;
    }

    // LN2 + relu -> global, layout [t][b][64]
#pragma unroll
    for (int r = 0; r < 4; ++r) {
        float y[4]; float s = 0.f, q = 0.f;
#pragma unroll
        for (int c = 0; c < 4; ++c) { y[c] = a2[r][c]; s += y[c]; q += y[c] * y[c]; }
#pragma unroll
        for (int o = 8; o; o >>= 1) {
            s += __shfl_xor_sync(0xffffffffu, s, o);
            q += __shfl_xor_sync(0xffffffffu, q, o);
        }
        float m = s * 0.015625f;
        float var = q * 0.015625f - m * m;
        float rs = rsqrtf(var + 1e-12f);
        int grow = row0 + r0 + r;
        int bb = grow >> 6, tt = grow & 63;   // T == 64
        float4 o4;
        o4.x = fmaxf((y[0] - m) * rs * sP[256 + c0 + 0] + sP[320 + c0 + 0], 0.f);
        o4.y = fmaxf((y[1] - m) * rs * sP[256 + c0 + 1] + sP[320 + c0 + 1], 0.f);
        o4.z = fmaxf((y[2] - m) * rs * sP[256 + c0 + 2] + sP[320 + c0 + 2], 0.f);
        o4.w = fmaxf((y[3] - m) * rs * sP[256 + c0 + 3] + sP[320 + c0 + 3], 0.f);
        *(float4*)(g_x2 + ((size_t)tt * Bn + bb) * 64 + c0) = o4;
    }
}

// =====================================================================
// Kernel 2: bidirectional LSTM scan. grid = (64, 2): 64 seq-chunks x dir.
// 256 threads. Thread = (seq-group sg = tid>>5) x (unit-pair up = tid&31):
// computes all 4 gates for units {2up, 2up+1} x 8 seqs, so c/h stay in regs.
// W [128][256] in smem; h transposed in smem; xs/ps computed via warp reduce.
// =====================================================================
__global__ void __launch_bounds__(256, 1) lstm_kernel(
    const float* __restrict__ Wf, const float* __restrict__ bfv,
    const float* __restrict__ Wb, const float* __restrict__ bbv,
    const float* __restrict__ wx, const float* __restrict__ bx,
    const float* __restrict__ wp, const float* __restrict__ bp)
{
    extern __shared__ float sm[];
    float* Ws = sm;                 // 128*256
    float* xT = Ws + 128 * 256;     // 64 x XS
    float* hT = xT + 64 * XS;       // 64 x XS

    const int dir = blockIdx.y;
    const int b0  = blockIdx.x * 64;
    const float* W    = dir ? Wb  : Wf;
    const float* bias = dir ? bbv : bfv;
    const int tid = threadIdx.x;

    for (int i = tid; i < 8192; i += 256) ((float4*)Ws)[i] = ((const float4*)W)[i];
    for (int i = tid; i < 64 * XS; i += 256) hT[i] = 0.f;

    const int up = tid & 31, sg = tid >> 5;
    const int u = up * 2, s0 = sg * 8;

    const float bi0 = bias[u],       bi1 = bias[u + 1];
    const float bj0 = bias[64 + u],  bj1 = bias[65 + u];
    const float bF0 = bias[128 + u], bF1 = bias[129 + u];
    const float bo0 = bias[192 + u], bo1 = bias[193 + u];
    const float wx0 = wx[u], wx1 = wx[u + 1];
    const float wp0 = wp[u], wp1 = wp[u + 1];
    const float bxs = bx[0], bps = bp[0];

    float c0r[8], c1r[8];
#pragma unroll
    for (int s = 0; s < 8; ++s) { c0r[s] = 0.f; c1r[s] = 0.f; }

    const int lr = tid >> 2, kq = tid & 3;

    for (int st = 0; st < Tn; ++st) {
        const int t = dir ? (Tn - 1 - st) : st;
        __syncthreads();   // prev hT writes visible; xT free
        {
            const float* src = g_x2 + ((size_t)t * Bn + b0 + lr) * 64 + kq * 16;
#pragma unroll
            for (int j = 0; j < 4; ++j) {
                float4 v = *(const float4*)(src + j * 4);
                int k = kq * 16 + j * 4;
                xT[(k + 0) * XS + lr] = v.x;
                xT[(k + 1) * XS + lr] = v.y;
                xT[(k + 2) * XS + lr] = v.z;
                xT[(k + 3) * XS + lr] = v.w;
            }
        }
        __syncthreads();

        float ai0[8], ai1[8], aj0[8], aj1[8], aF0[8], aF1[8], ao0[8], ao1[8];
#pragma unroll
        for (int s = 0; s < 8; ++s) {
            ai0[s] = bi0; ai1[s] = bi1; aj0[s] = bj0; aj1[s] = bj1;
            aF0[s] = bF0; aF1[s] = bF1; ao0[s] = bo0; ao1[s] = bo1;
        }
        const float* xb = xT + s0;
        const float* hb = hT + s0;

#pragma unroll 2
        for (int k = 0; k < 64; ++k) {
            float xv[8];
            *(float4*)(xv)     = *(const float4*)(xb + k * XS);
            *(float4*)(xv + 4) = *(const float4*)(xb + k * XS + 4);
            const float* wr = Ws + k * 256 + u;
            float2 wi  = *(const float2*)(wr);
            float2 wj  = *(const float2*)(wr + 64);
            float2 wf2 = *(const float2*)(wr + 128);
            float2 wo  = *(const float2*)(wr + 192);
#pragma unroll
            for (int s = 0; s < 8; ++s) {
                ai0[s] += xv[s] * wi.x;  ai1[s] += xv[s] * wi.y;
                aj0[s] += xv[s] * wj.x;  aj1[s] += xv[s] * wj.y;
                aF0[s] += xv[s] * wf2.x; aF1[s] += xv[s] * wf2.y;
                ao0[s] += xv[s] * wo.x;  ao1[s] += xv[s] * wo.y;
            }
        }
#pragma unroll 2
        for (int k = 0; k < 64; ++k) {
            float hv[8];
            *(float4*)(hv)     = *(const float4*)(hb + k * XS);
            *(float4*)(hv + 4) = *(const float4*)(hb + k * XS + 4);
            const float* wr = Ws + (64 + k) * 256 + u;
            float2 wi  = *(const float2*)(wr);
            float2 wj  = *(const float2*)(wr + 64);
            float2 wf2 = *(const float2*)(wr + 128);
            float2 wo  = *(const float2*)(wr + 192);
#pragma unroll
            for (int s = 0; s < 8; ++s) {
                ai0[s] += hv[s] * wi.x;  ai1[s] += hv[s] * wi.y;
                aj0[s] += hv[s] * wj.x;  aj1[s] += hv[s] * wj.y;
                aF0[s] += hv[s] * wf2.x; aF1[s] += hv[s] * wf2.y;
                ao0[s] += hv[s] * wo.x;  ao1[s] += hv[s] * wo.y;
            }
        }
        __syncthreads();   // all hT/xT reads done before hT overwrite

        float px[8], pq[8];
#pragma unroll
        for (int s = 0; s < 8; ++s) {
            float ig = sigf(ai0[s]);
            float jg = tanh_fast(aj0[s]);
            float fg = sigf(aF0[s] + 1.f);
            float og = sigf(ao0[s]);
            float cn = c0r[s] * fg + ig * jg;
            c0r[s] = cn;
            float h0 = tanh_fast(cn) * og;

            ig = sigf(ai1[s]);
            jg = tanh_fast(aj1[s]);
            fg = sigf(aF1[s] + 1.f);
            og = sigf(ao1[s]);
            cn = c1r[s] * fg + ig * jg;
            c1r[s] = cn;
            float h1 = tanh_fast(cn) * og;

            hT[u * XS + s0 + s]       = h0;
            hT[(u + 1) * XS + s0 + s] = h1;
            px[s] = h0 * wx0 + h1 * wx1;
            pq[s] = h0 * wp0 + h1 * wp1;
        }
#pragma unroll
        for (int o = 16; o; o >>= 1) {
#pragma unroll
            for (int s = 0; s < 8; ++s) {
                px[s] += __shfl_xor_sync(0xffffffffu, px[s], o);
                pq[s] += __shfl_xor_sync(0xffffffffu, pq[s], o);
            }
        }
        if (up < 8) {
            size_t row = (size_t)dir * Bn + b0 + s0 + up;
            g_xs[row * Tn + t] = px[up] + bxs;
            g_ps[row * Tn + t] = pq[up] + bps;
        }
    }
}

// =====================================================================
// Kernel 3: attention head. warp per sequence; 8 seqs / block.
// p = softmax(relu(LN(ps)) @ W3 + b3); out = sum(p * xs)
// =====================================================================
__global__ void __launch_bounds__(256) attn_kernel(
    const float* __restrict__ gp, const float* __restrict__ bep,
    const float* __restrict__ W3, const float* __restrict__ b3,
    float* __restrict__ out)
{
    __shared__ float sW3[4096];
    __shared__ float sb3[64];
    const int tid = threadIdx.x;
    for (int i = tid; i < 1024; i += 256) ((float4*)sW3)[i] = ((const float4*)W3)[i];
    if (tid < 64) sb3[tid] = b3[tid];
    __syncthreads();

    const int lane = tid & 31, w = tid >> 5;
    const int seq = blockIdx.x * 8 + w;

    const float* psr = g_ps + (size_t)seq * Tn;
    float v0 = psr[lane], v1 = psr[lane + 32];
    float s = v0 + v1, q = v0 * v0 + v1 * v1;
#pragma unroll
    for (int o = 16; o; o >>= 1) {
        s += __shfl_xor_sync(0xffffffffu, s, o);
        q += __shfl_xor_sync(0xffffffffu, q, o);
    }
    float m = s * 0.015625f;
    float var = q * 0.015625f - m * m;
    float rs = rsqrtf(var + 1e-12f);
    float p0 = fmaxf((v0 - m) * rs * gp[lane]      + bep[lane],      0.f);
    float p1 = fmaxf((v1 - m) * rs * gp[lane + 32] + bep[lane + 32], 0.f);

    float l0 = sb3[lane], l1 = sb3[lane + 32];
#pragma unroll 8
    for (int tt = 0; tt < 32; ++tt) {
        float pv = __shfl_sync(0xffffffffu, p0, tt);
        l0 += pv * sW3[tt * 64 + lane];
        l1 += pv * sW3[tt * 64 + lane + 32];
    }
#pragma unroll 8
    for (int tt = 0; tt < 32; ++tt) {
        float pv = __shfl_sync(0xffffffffu, p1, tt);
        l0 += pv * sW3[(32 + tt) * 64 + lane];
        l1 += pv * sW3[(32 + tt) * 64 + lane + 32];
    }

    float mx = fmaxf(l0, l1);
#pragma unroll
    for (int o = 16; o; o >>= 1) mx = fmaxf(mx, __shfl_xor_sync(0xffffffffu, mx, o));
    float e0 = __expf(l0 - mx), e1 = __expf(l1 - mx);
    float se = e0 + e1;
    const float* xsr = g_xs + (size_t)seq * Tn;
    float rsum = e0 * xsr[lane] + e1 * xsr[lane + 32];
#pragma unroll
    for (int o = 16; o; o >>= 1) {
        se   += __shfl_xor_sync(0xffffffffu, se, o);
        rsum += __shfl_xor_sync(0xffffffffu, rsum, o);
    }
    if (lane == 0) out[seq] = rsum / se;
}

// =====================================================================
extern "C" void kernel_launch(void* const* d_in, const int* in_sizes, int n_in,
                              void* d_out, int out_size)
{
    const float* obs = (const float*)d_in[0];
    const float* act = (const float*)d_in[1];
    const float* W1  = (const float*)d_in[2];
    const float* b1  = (const float*)d_in[3];
    const float* g1  = (const float*)d_in[4];
    const float* be1 = (const float*)d_in[5];
    const float* W2  = (const float*)d_in[6];
    const float* b2  = (const float*)d_in[7];
    const float* g2  = (const float*)d_in[8];
    const float* be2 = (const float*)d_in[9];
    const float* Wf  = (const float*)d_in[10];
    const float* bf  = (const float*)d_in[11];
    const float* Wb  = (const float*)d_in[12];
    const float* bb  = (const float*)d_in[13];
    const float* wx  = (const float*)d_in[14];
    const float* bx  = (const float*)d_in[15];
    const float* wp  = (const float*)d_in[16];
    const float* bp  = (const float*)d_in[17];
    const float* gp  = (const float*)d_in[18];
    const float* bep = (const float*)d_in[19];
    const float* W3  = (const float*)d_in[20];
    const float* b3  = (const float*)d_in[21];
    float* out = (float*)d_out;

    const int trunk_smem = (128 * 64 + 96 * 64 + 64 * STR + 96 * STR + 6 * 64) * 4;
    const int lstm_smem  = (128 * 256 + 2 * 64 * XS) * 4;
    cudaFuncSetAttribute(trunk_kernel, cudaFuncAttributeMaxDynamicSharedMemorySize, trunk_smem);
    cudaFuncSetAttribute(lstm_kernel,  cudaFuncAttributeMaxDynamicSharedMemorySize, lstm_smem);

    trunk_kernel<<<4096, 256, trunk_smem>>>(obs, act, W1, b1, g1, be1, W2, b2, g2, be2);

    dim3 lg(64, 2);
    lstm_kernel<<<lg, 256, lstm_smem>>>(Wf, bf, Wb, bb, wx, bx, wp, bp);

    attn_kernel<<<1024, 256>>>(gp, bep, W3, b3, out);
}